// round 7
// baseline (speedup 1.0000x reference)
#include <cuda_runtime.h>
#include <cuda_fp16.h>

// Problem geometry (fixed per reference setup_inputs)
#define B_ 2
#define D_ 160
#define H_ 192
#define W_ 160
constexpr size_t N_  = (size_t)B_ * D_ * H_ * W_;   // 9,830,400
constexpr size_t HW_ = (size_t)H_ * W_;
#define G8_ 20   // 8-wide w groups per row

// Intermediate: 5 channels (I_s, J_s, I2_s, J2_s, IJ_s), W+H convolved, fp16.
__device__ __half g_A[5 * N_];
__device__ double g_acc;
__device__ unsigned g_tk;

// ---------------------------------------------------------------------------
// Helpers
// ---------------------------------------------------------------------------
__device__ __forceinline__ float4 f4z() { return make_float4(0.f, 0.f, 0.f, 0.f); }
__device__ __forceinline__ unsigned h2u(__half2 h) { return *(unsigned*)&h; }
__device__ __forceinline__ __half2 u2h(unsigned u) { return *(__half2*)&u; }

// 9-tap window sums: r[l] = sum x[l .. l+8], l = 0..7 (x has 16 entries).
__device__ __forceinline__ void win9_8(const float* x, float* r) {
    float s = x[0]+x[1]+x[2]+x[3]+x[4]+x[5]+x[6]+x[7]+x[8];
    r[0] = s;
#pragma unroll
    for (int j = 1; j < 8; j++) { s += x[j+8] - x[j-1]; r[j] = s; }
}

// Fold 8 fp32 window values into 4 half2 accumulators with sign.
__device__ __forceinline__ void fold(__half2* S, const float* r, bool add) {
#pragma unroll
    for (int j = 0; j < 4; j++) {
        __half2 w = __floats2half2_rn(r[2*j], r[2*j+1]);
        S[j] = add ? __hadd2(S[j], w) : __hsub2(S[j], w);
    }
}

// ---------------------------------------------------------------------------
// Fused pass 1+2: W-window (9-tap prefix+slide over 16 taps, 8 lanes/thread)
// + H-window (re-read sliding, accumulators in half2). fp16 output.
// Thread = (plane, h-chunk of 24, 8-wide w group).
// ---------------------------------------------------------------------------
__global__ void __launch_bounds__(128) k_p12(const float* __restrict__ I,
                                             const float* __restrict__ J) {
    const int t     = blockIdx.x * blockDim.x + threadIdx.x;  // 51,200 threads
    const int g     = t % G8_;                // 8-lane group 0..19
    const int ch    = (t / G8_) & 7;          // h-chunk 0..7
    const int plane = t / (G8_ * 8);          // b*D + d
    const int h0    = ch * 24;

    if (t == 0) { g_acc = 0.0; g_tk = 0u; }

    const size_t pbase = (size_t)plane * HW_;
    const float4* __restrict__ I4 = (const float4*)(I + pbase);
    const float4* __restrict__ J4 = (const float4*)(J + pbase);

    __half2 S[5][4];
    const __half2 hz = __floats2half2_rn(0.f, 0.f);
#pragma unroll
    for (int c = 0; c < 5; c++)
#pragma unroll
        for (int j = 0; j < 4; j++) S[c][j] = hz;

    auto accum = [&](int hr, bool add) {
        const int rb = hr * 40;               // float4 groups per row
        const int g4 = g * 2;
        float4 qa[4], qb[4];
#pragma unroll
        for (int q = 0; q < 4; q++) {
            const int gg = g4 - 1 + q;
            const bool ok = (gg >= 0) && (gg < 40);
            qa[q] = ok ? __ldg(I4 + rb + gg) : f4z();
            qb[q] = ok ? __ldg(J4 + rb + gg) : f4z();
        }
        float a[16] = {qa[0].x,qa[0].y,qa[0].z,qa[0].w, qa[1].x,qa[1].y,qa[1].z,qa[1].w,
                       qa[2].x,qa[2].y,qa[2].z,qa[2].w, qa[3].x,qa[3].y,qa[3].z,qa[3].w};
        float b[16] = {qb[0].x,qb[0].y,qb[0].z,qb[0].w, qb[1].x,qb[1].y,qb[1].z,qb[1].w,
                       qb[2].x,qb[2].y,qb[2].z,qb[2].w, qb[3].x,qb[3].y,qb[3].z,qb[3].w};

        float r[8];
        win9_8(a, r); fold(S[0], r, add);
        win9_8(b, r); fold(S[1], r, add);
        float p[16];
#pragma unroll
        for (int i = 0; i < 16; i++) p[i] = a[i] * a[i];
        win9_8(p, r); fold(S[2], r, add);
#pragma unroll
        for (int i = 0; i < 16; i++) p[i] = b[i] * b[i];
        win9_8(p, r); fold(S[3], r, add);
#pragma unroll
        for (int i = 0; i < 16; i++) p[i] = a[i] * b[i];
        win9_8(p, r); fold(S[4], r, add);
    };

    // Prologue: H-window for output row h0 (rows h0-4 .. h0+4)
#pragma unroll 1
    for (int k = 0; k < 9; k++) {
        const int hr = h0 - 4 + k;
        if (hr >= 0 && hr < H_) accum(hr, true);
    }

#pragma unroll 2
    for (int i = 0; i < 24; i++) {
        const int ho = h0 + i;
        const size_t o = pbase + (size_t)ho * W_ + (size_t)g * 8;
#pragma unroll
        for (int c = 0; c < 5; c++)
            *(uint4*)&g_A[c * N_ + o] =
                make_uint4(h2u(S[c][0]), h2u(S[c][1]), h2u(S[c][2]), h2u(S[c][3]));

        const int hp = ho + 5, hm = ho - 4;
        if (hp < H_)  accum(hp, true);
        if (hm >= 0)  accum(hm, false);
    }
}

// ---------------------------------------------------------------------------
// Pass 3: 9-tap box sum along D in half2 arithmetic (8 lanes/thread, uint4
// loads), fp32 cc epilogue, double block reduction, last-block finalization.
// ---------------------------------------------------------------------------
__global__ void __launch_bounds__(256) k_p3(float* __restrict__ out) {
    const int t  = blockIdx.x * blockDim.x + threadIdx.x;  // 61,440 threads
    const int wv = t % G8_;
    const int h  = (t / G8_) % H_;
    const int ch = (t / (G8_ * H_)) & 7;      // d-chunk 0..7 (20 outputs each)
    const int b  = t / (G8_ * H_ * 8);
    const int d0 = ch * 20;

    const size_t colbase = (size_t)b * D_ * HW_ + (size_t)h * W_ + (size_t)wv * 8;

    __half2 S[5][4];
    const __half2 hz = __floats2half2_rn(0.f, 0.f);
#pragma unroll
    for (int c = 0; c < 5; c++)
#pragma unroll
        for (int j = 0; j < 4; j++) S[c][j] = hz;

    // Prologue: window for output d0 (slices d0-4 .. d0+4)
#pragma unroll 1
    for (int k = 0; k < 9; k++) {
        const int d = d0 - 4 + k;
        if (d >= 0 && d < D_) {
            const size_t o = colbase + (size_t)d * HW_;
#pragma unroll
            for (int c = 0; c < 5; c++) {
                const uint4 v = __ldg((const uint4*)&g_A[c * N_ + o]);
                S[c][0] = __hadd2(S[c][0], u2h(v.x));
                S[c][1] = __hadd2(S[c][1], u2h(v.y));
                S[c][2] = __hadd2(S[c][2], u2h(v.z));
                S[c][3] = __hadd2(S[c][3], u2h(v.w));
            }
        }
    }

    const float inv = 1.0f / 729.0f;
    float lacc = 0.f;
    const uint4 uz = make_uint4(0u, 0u, 0u, 0u);

#pragma unroll 2
    for (int i = 0; i < 20; i++) {
        const int d  = d0 + i;
        const int dp = d + 5;
        const int dm = d - 4;
        const bool pok = (dp < D_);
        const bool mok = (dm >= 0);
        const size_t op = colbase + (size_t)(pok ? dp : 0) * HW_;
        const size_t om = colbase + (size_t)(mok ? dm : 0) * HW_;

        uint4 av[5], sv[5];
#pragma unroll
        for (int c = 0; c < 5; c++) {
            av[c] = pok ? __ldg((const uint4*)&g_A[c * N_ + op]) : uz;
            sv[c] = mok ? __ldg((const uint4*)&g_A[c * N_ + om]) : uz;
        }

        // cc epilogue in fp32 for the 8 lanes of the current window S
        float f[5][8];
#pragma unroll
        for (int c = 0; c < 5; c++)
#pragma unroll
            for (int j = 0; j < 4; j++) {
                const float2 fv = __half22float2(S[c][j]);
                f[c][2*j]   = fv.x;
                f[c][2*j+1] = fv.y;
            }
#pragma unroll
        for (int l = 0; l < 8; l++) {
            const float cross = fmaf(-f[0][l] * inv, f[1][l], f[4][l]);
            const float ivar  = fmaf(-f[0][l] * inv, f[0][l], f[2][l]);
            const float jvar  = fmaf(-f[1][l] * inv, f[1][l], f[3][l]);
            lacc += __fdividef(cross * cross, fmaf(ivar, jvar, 1e-5f));
        }

        // Slide window in half2
        const unsigned* pa;
        const unsigned* ps;
#pragma unroll
        for (int c = 0; c < 5; c++) {
            pa = (const unsigned*)&av[c];
            ps = (const unsigned*)&sv[c];
#pragma unroll
            for (int j = 0; j < 4; j++)
                S[c][j] = __hsub2(__hadd2(S[c][j], u2h(pa[j])), u2h(ps[j]));
        }
    }

    // Block reduction in double, one atomic per block, last-block finalizes.
    double v = (double)lacc;
#pragma unroll
    for (int off = 16; off; off >>= 1)
        v += __shfl_down_sync(0xffffffffu, v, off);

    __shared__ double sm[8];
    const int lane = threadIdx.x & 31;
    const int wid  = threadIdx.x >> 5;
    if (lane == 0) sm[wid] = v;
    __syncthreads();
    if (wid == 0) {
        v = (lane < 8) ? sm[lane] : 0.0;
        v += __shfl_down_sync(0xffffffffu, v, 4);
        v += __shfl_down_sync(0xffffffffu, v, 2);
        v += __shfl_down_sync(0xffffffffu, v, 1);
        if (lane == 0) {
            atomicAdd(&g_acc, v);
            __threadfence();
            const unsigned tk = atomicAdd(&g_tk, 1u);
            if (tk == gridDim.x - 1) {
                __threadfence();
                out[0] = (float)(-g_acc / (double)N_);
            }
        }
    }
}

// ---------------------------------------------------------------------------
extern "C" void kernel_launch(void* const* d_in, const int* in_sizes, int n_in,
                              void* d_out, int out_size) {
    const float* y_pred = (const float*)d_in[0];
    const float* y_true = (const float*)d_in[1];

    // 51,200 threads: (plane, h-chunk of 24, w-group of 8)
    k_p12<<<(B_ * D_ * 8 * G8_) / 128, 128>>>(y_true, y_pred);

    // 61,440 threads: (b, d-chunk of 20, h, w-group of 8), fused finalization
    k_p3<<<(B_ * 8 * H_ * G8_) / 256, 256>>>((float*)d_out);
}

// round 8
// speedup vs baseline: 1.2198x; 1.2198x over previous
#include <cuda_runtime.h>
#include <cuda_fp16.h>

// Problem geometry (fixed per reference setup_inputs)
#define B_ 2
#define D_ 160
#define H_ 192
#define W_ 160
constexpr size_t N_  = (size_t)B_ * D_ * H_ * W_;   // 9,830,400
constexpr size_t HW_ = (size_t)H_ * W_;
#define WG_ 40   // float4 groups along w
#define NHC_ 12  // h-chunks (16 rows each)
#define NDC_ 16  // d-chunks (10 slices each)

// Intermediate: 5 channels (I_s, J_s, I2_s, J2_s, IJ_s), W+H convolved, fp16.
__device__ __half g_A[5 * N_];
__device__ double g_acc;
__device__ unsigned g_tk;

// ---------------------------------------------------------------------------
// Helpers
// ---------------------------------------------------------------------------
__device__ __forceinline__ float4 f4z() { return make_float4(0.f, 0.f, 0.f, 0.f); }

__device__ __forceinline__ uint2 f4_to_h4(float4 v) {
    __half2 lo = __floats2half2_rn(v.x, v.y);
    __half2 hi = __floats2half2_rn(v.z, v.w);
    uint2 r;
    r.x = *(const unsigned*)&lo;
    r.y = *(const unsigned*)&hi;
    return r;
}

__device__ __forceinline__ float4 h4_to_f4(uint2 u) {
    __half2 lo = *(const __half2*)&u.x;
    __half2 hi = *(const __half2*)&u.y;
    float2 a = __half22float2(lo);
    float2 b = __half22float2(hi);
    return make_float4(a.x, a.y, b.x, b.y);
}

// 9-tap window sums per lane from a 12-float sequence x[0..11] (x[0] = w-4).
__device__ __forceinline__ float4 win9(const float* x) {
    float s = x[0]+x[1]+x[2]+x[3]+x[4]+x[5]+x[6]+x[7]+x[8];
    float4 r;
    r.x = s;
    s += x[9]  - x[0]; r.y = s;
    s += x[10] - x[1]; r.z = s;
    s += x[11] - x[2]; r.w = s;
    return r;
}

// ---------------------------------------------------------------------------
// Fused pass 1+2: 9-tap box sums along W and H, float4-vectorized, fp16 out.
// Thread = (plane, h-chunk of 16, 4-wide w group). Slides along h via
// re-read: S += Wrow(h+5) - Wrow(h-4) (subtract row is an L1/L2 hit).
// ---------------------------------------------------------------------------
__global__ void __launch_bounds__(256) k_p12(const float* __restrict__ I,
                                             const float* __restrict__ J) {
    const int t     = blockIdx.x * blockDim.x + threadIdx.x;  // 153,600 threads
    const int g     = t % WG_;                 // f4 group 0..39
    const int ch    = (t / WG_) % NHC_;        // h-chunk 0..11
    const int plane = t / (WG_ * NHC_);        // b*D + d
    const int h0    = ch * 16;

    if (t == 0) { g_acc = 0.0; g_tk = 0u; }

    const size_t pbase = (size_t)plane * HW_;
    const float4* __restrict__ I4 = (const float4*)(I + pbase);
    const float4* __restrict__ J4 = (const float4*)(J + pbase);

    float4 S0 = f4z(), S1 = f4z(), S2 = f4z(), S3 = f4z(), S4 = f4z();

    auto accum = [&](int hr, float sg) {
        const int rb = hr * WG_;
        float4 qa0 = (g > 0)       ? __ldg(I4 + rb + g - 1) : f4z();
        float4 qa1 =                 __ldg(I4 + rb + g);
        float4 qa2 = (g < WG_ - 1) ? __ldg(I4 + rb + g + 1) : f4z();
        float4 qb0 = (g > 0)       ? __ldg(J4 + rb + g - 1) : f4z();
        float4 qb1 =                 __ldg(J4 + rb + g);
        float4 qb2 = (g < WG_ - 1) ? __ldg(J4 + rb + g + 1) : f4z();

        float a[12] = {qa0.x,qa0.y,qa0.z,qa0.w, qa1.x,qa1.y,qa1.z,qa1.w, qa2.x,qa2.y,qa2.z,qa2.w};
        float b[12] = {qb0.x,qb0.y,qb0.z,qb0.w, qb1.x,qb1.y,qb1.z,qb1.w, qb2.x,qb2.y,qb2.z,qb2.w};

        float4 w0 = win9(a);
        float4 w1 = win9(b);
        float p[12];
#pragma unroll
        for (int i = 0; i < 12; i++) p[i] = a[i] * a[i];
        float4 w2 = win9(p);
#pragma unroll
        for (int i = 0; i < 12; i++) p[i] = b[i] * b[i];
        float4 w3 = win9(p);
#pragma unroll
        for (int i = 0; i < 12; i++) p[i] = a[i] * b[i];
        float4 w4 = win9(p);

        S0.x += sg*w0.x; S0.y += sg*w0.y; S0.z += sg*w0.z; S0.w += sg*w0.w;
        S1.x += sg*w1.x; S1.y += sg*w1.y; S1.z += sg*w1.z; S1.w += sg*w1.w;
        S2.x += sg*w2.x; S2.y += sg*w2.y; S2.z += sg*w2.z; S2.w += sg*w2.w;
        S3.x += sg*w3.x; S3.y += sg*w3.y; S3.z += sg*w3.z; S3.w += sg*w3.w;
        S4.x += sg*w4.x; S4.y += sg*w4.y; S4.z += sg*w4.z; S4.w += sg*w4.w;
    };

    // Prologue: H-window for output row h0 (rows h0-4 .. h0+4)
#pragma unroll
    for (int k = -4; k <= 4; k++) {
        const int hr = h0 + k;
        if (hr >= 0 && hr < H_) accum(hr, 1.f);
    }

#pragma unroll 2
    for (int i = 0; i < 16; i++) {
        const int h = h0 + i;
        const size_t o = pbase + (size_t)h * W_ + (size_t)g * 4;
        *(uint2*)&g_A[0*N_ + o] = f4_to_h4(S0);
        *(uint2*)&g_A[1*N_ + o] = f4_to_h4(S1);
        *(uint2*)&g_A[2*N_ + o] = f4_to_h4(S2);
        *(uint2*)&g_A[3*N_ + o] = f4_to_h4(S3);
        *(uint2*)&g_A[4*N_ + o] = f4_to_h4(S4);

        const int hp = h + 5, hm = h - 4;
        if (hp < H_)  accum(hp,  1.f);
        if (hm >= 0)  accum(hm, -1.f);
    }
}

// ---------------------------------------------------------------------------
// Pass 3: 9-tap box sum along D over fp16 intermediates (fp32 accumulation),
// float4 over w, d-chunked x16, re-read sliding window. Fused cc + reduction
// + last-block finalization.
// ---------------------------------------------------------------------------
__global__ void __launch_bounds__(256) k_p3(float* __restrict__ out) {
    const int t  = blockIdx.x * blockDim.x + threadIdx.x;  // 245,760 threads
    const int wv = t % WG_;
    const int h  = (t / WG_) % H_;
    const int ch = (t / (WG_ * H_)) % NDC_;   // d-chunk 0..15 (10 outputs each)
    const int b  = t / (WG_ * H_ * NDC_);
    const int d0 = ch * 10;

    const size_t colbase = (size_t)b * D_ * HW_ + (size_t)h * W_ + (size_t)wv * 4;

    float4 S[5];
#pragma unroll
    for (int c = 0; c < 5; c++) S[c] = f4z();

#pragma unroll
    for (int k = -4; k <= 4; k++) {
        const int d = d0 + k;
        if (d >= 0 && d < D_) {
            const size_t o = colbase + (size_t)d * HW_;
#pragma unroll
            for (int c = 0; c < 5; c++) {
                const float4 v = h4_to_f4(__ldg((const uint2*)&g_A[c * N_ + o]));
                S[c].x += v.x; S[c].y += v.y; S[c].z += v.z; S[c].w += v.w;
            }
        }
    }

    const float inv = 1.0f / 729.0f;
    float lacc = 0.f;

#pragma unroll 5
    for (int i = 0; i < 10; i++) {
        const int d  = d0 + i;
        const int dp = d + 5;
        const int dm = d - 4;

        float4 av[5], sv[5];
        const bool pok = (dp < D_);
        const bool mok = (dm >= 0);
        const size_t op = colbase + (size_t)(pok ? dp : 0) * HW_;
        const size_t om = colbase + (size_t)(mok ? dm : 0) * HW_;
#pragma unroll
        for (int c = 0; c < 5; c++) {
            av[c] = pok ? h4_to_f4(__ldg((const uint2*)&g_A[c * N_ + op])) : f4z();
            sv[c] = mok ? h4_to_f4(__ldg((const uint2*)&g_A[c * N_ + om])) : f4z();
        }

        {
            const float* s0 = (const float*)&S[0];
            const float* s1 = (const float*)&S[1];
            const float* s2 = (const float*)&S[2];
            const float* s3 = (const float*)&S[3];
            const float* s4 = (const float*)&S[4];
#pragma unroll
            for (int l = 0; l < 4; l++) {
                const float cross = fmaf(-s0[l] * inv, s1[l], s4[l]);
                const float ivar  = fmaf(-s0[l] * inv, s0[l], s2[l]);
                const float jvar  = fmaf(-s1[l] * inv, s1[l], s3[l]);
                lacc += __fdividef(cross * cross, fmaf(ivar, jvar, 1e-5f));
            }
        }

#pragma unroll
        for (int c = 0; c < 5; c++) {
            S[c].x += av[c].x - sv[c].x;
            S[c].y += av[c].y - sv[c].y;
            S[c].z += av[c].z - sv[c].z;
            S[c].w += av[c].w - sv[c].w;
        }
    }

    // Block reduction in double, one atomic per block, last-block finalizes.
    double v = (double)lacc;
#pragma unroll
    for (int off = 16; off; off >>= 1)
        v += __shfl_down_sync(0xffffffffu, v, off);

    __shared__ double sm[8];
    const int lane = threadIdx.x & 31;
    const int wid  = threadIdx.x >> 5;
    if (lane == 0) sm[wid] = v;
    __syncthreads();
    if (wid == 0) {
        v = (lane < 8) ? sm[lane] : 0.0;
        v += __shfl_down_sync(0xffffffffu, v, 4);
        v += __shfl_down_sync(0xffffffffu, v, 2);
        v += __shfl_down_sync(0xffffffffu, v, 1);
        if (lane == 0) {
            atomicAdd(&g_acc, v);
            __threadfence();
            const unsigned tk = atomicAdd(&g_tk, 1u);
            if (tk == gridDim.x - 1) {
                __threadfence();
                out[0] = (float)(-g_acc / (double)N_);
            }
        }
    }
}

// ---------------------------------------------------------------------------
extern "C" void kernel_launch(void* const* d_in, const int* in_sizes, int n_in,
                              void* d_out, int out_size) {
    const float* y_pred = (const float*)d_in[0];
    const float* y_true = (const float*)d_in[1];

    // 153,600 threads: (plane, h-chunk of 16, w/4)
    k_p12<<<(B_ * D_ * NHC_ * WG_) / 256, 256>>>(y_true, y_pred);

    // 245,760 threads: (b, d-chunk of 10, h, w/4), fused finalization
    k_p3<<<(B_ * NDC_ * H_ * WG_) / 256, 256>>>((float*)d_out);
}